// round 7
// baseline (speedup 1.0000x reference)
#include <cuda_runtime.h>

#define NB 128
#define NT 1024
#define ND 3
#define NH 512
#define NC 3
#define NSLICE 16      // h-slices per batch group = CTAs per group
#define HS 32          // h per slice
#define NGRP 8         // batch groups
#define BGr 16         // batch rows per group
#define KS 32          // k per k-slice (per warp)
#define NKS 16         // k-slices = warps
#define THREADS 512

typedef unsigned long long u64;

// dataflow flags: flag[g][t][j] flips parity when group g's slice j of step t
// is published. Zero-initialized; every launch flips every slot exactly once,
// so pre-launch parity is uniform and can be probed from any late-written slot.
__device__ int g_flag[NGRP][NT][NSLICE];

static __device__ __forceinline__ u64 pack2(float x, float y) {
    u64 v; asm("mov.b64 %0, {%1, %2};" : "=l"(v) : "f"(x), "f"(y)); return v;
}
static __device__ __forceinline__ float2 unpack2(u64 v) {
    float2 f; asm("mov.b64 {%0, %1}, %2;" : "=f"(f.x), "=f"(f.y) : "l"(v)); return f;
}
static __device__ __forceinline__ u64 ffma2(u64 a, u64 b, u64 c) {
    u64 d; asm("fma.rn.f32x2 %0, %1, %2, %3;" : "=l"(d) : "l"(a), "l"(b), "l"(c)); return d;
}
static __device__ __forceinline__ u64 fadd2(u64 a, u64 b) {
    u64 d; asm("add.rn.f32x2 %0, %1, %2;" : "=l"(d) : "l"(a), "l"(b)); return d;
}

// all lanes poll (uniform address -> 1 sector); acquire gives every lane the
// ordering it needs for its subsequent LDGs of the published slice.
static __device__ __forceinline__ void wait_flag(const int* pf, int stale) {
    int v;
    do {
        asm volatile("ld.acquire.gpu.global.s32 %0, [%1];"
                     : "=r"(v) : "l"(pf) : "memory");
    } while (v == stale);
}

extern __shared__ float smem_f[];

// One persistent kernel, grid 128 = 8 groups x 16 slices, 1 CTA/SM.
// compute role: warp ks consumes k-block ks (= slice ks of r(t-1)) for all 16 rows.
// reduce  role: warp rb (=ks) owns batch row rb, lane hh owns h = slice*32+hh.
__global__ void __launch_bounds__(THREADS, 1)
flipflop_main(const float* __restrict__ inputs,
              const float* __restrict__ Wv,
              const float* __restrict__ Pv,
              const float* __restrict__ bv,
              const float* __restrict__ Wz,
              const float* __restrict__ Pz,
              const float* __restrict__ bz,
              const float* __restrict__ fcW,
              const float* __restrict__ fcb,
              float* __restrict__ out,
              float* __restrict__ hidden)
{
    u64* psum = (u64*)smem_f;                 // [BGr][NKS][HS] u64 = 64 KB

    const int tid   = threadIdx.x;
    const int grp   = blockIdx.x >> 4;
    const int slice = blockIdx.x & 15;
    const int ks    = tid >> 5;               // warp id = k-block = reduce row
    const int hh    = tid & 31;
    const int hg    = slice * HS + hh;        // global h for this lane
    const int gb    = grp * BGr;

    // ---- weight slice into registers: k-pairs, z and v separate ----
    u64 wz[16], wv[16];
    {
        const u64* zr = (const u64*)(Wz + (size_t)hg * NH + ks * KS);
        const u64* vr = (const u64*)(Wv + (size_t)hg * NH + ks * KS);
        #pragma unroll
        for (int j = 0; j < 16; ++j) { wz[j] = zr[j]; wv[j] = vr[j]; }
    }

    // pre-launch parity probe. Slot [grp][NT-1][ks] is written only at step
    // NT-1 (every CTA is lock-stepped within +-1 step by the flags), so this
    // relaxed read cannot race with this launch's writes.
    int par;
    asm volatile("ld.relaxed.gpu.global.s32 %0, [%1];"
                 : "=r"(par) : "l"(&g_flag[grp][NT-1][ks]));
    const int ready = par ^ 1;

    // ---- reduce-role constants ----
    const int rb = ks;
    const float pz0 = Pz[hg*3+0], pz1 = Pz[hg*3+1], pz2 = Pz[hg*3+2];
    float pm0 = 0.f, pm1 = 0.f, pm2 = 0.f;    // P_m: bottom half zeroed
    if (hg < NH/2) { pm0 = Pv[hg*3+0]; pm1 = Pv[hg*3+1]; pm2 = Pv[hg*3+2]; }
    const float bzr = bz[hg];
    const float bvr = bv[hg];

    const float* xrow = inputs + (size_t)(gb + rb) * NT * ND;
    float*       hout = hidden + ((size_t)(gb + rb) * NT) * NH + hg;  // step stride NH

    // compute-role base: k-block ks of row gb+b at step t-1
    const size_t rowstep = (size_t)NT * NH;

    float r_prev = 0.f;                       // r(t-1)[rb][hg], register-resident

    for (int t = 0; t < NT; ++t) {
        const float x0 = xrow[t*3+0], x1 = xrow[t*3+1], x2 = xrow[t*3+2];

        if (t > 0) {
            // wait for slice ks of step t-1, then consume it for all 16 rows
            wait_flag(&g_flag[grp][t-1][ks], par);

            const float* rbase = hidden + ((size_t)gb * NT + (t - 1)) * NH + ks * KS;
            #pragma unroll 1
            for (int b = 0; b < BGr; ++b) {
                const ulonglong2* rp = (const ulonglong2*)(rbase + (size_t)b * rowstep);
                u64 az0 = 0ull, az1 = 0ull, av0 = 0ull, av1 = 0ull;
                #pragma unroll
                for (int kk = 0; kk < 8; ++kk) {
                    ulonglong2 q = rp[kk];            // 4 r values (uniform across lanes)
                    az0 = ffma2(q.x, wz[kk*2+0], az0);
                    av0 = ffma2(q.x, wv[kk*2+0], av0);
                    az1 = ffma2(q.y, wz[kk*2+1], az1);
                    av1 = ffma2(q.y, wv[kk*2+1], av1);
                }
                const float2 fz = unpack2(fadd2(az0, az1));
                const float2 fv = unpack2(fadd2(av0, av1));
                psum[(b * NKS + ks) * HS + hh] = pack2(fz.x + fz.y, fv.x + fv.y);
            }
            __syncthreads();
        }

        // ---- reduce + gates: thread owns (rb, hg) ----
        float sz = 0.f, sv = 0.f;
        if (t > 0) {
            #pragma unroll
            for (int k = 0; k < NKS; ++k) {
                float2 p = unpack2(psum[(rb * NKS + k) * HS + hh]);
                sz += p.x; sv += p.y;
            }
        }
        const float az = sz + x0*pz0 + x1*pz1 + x2*pz2 + bzr;
        const float av = sv + x0*pm0 + x1*pm1 + x2*pm2 + bvr;
        const float z  = 1.f / (1.f + __expf(-az));
        const float c  = 1.f / (1.f + __expf(-av));
        const float rn = fmaf(z, c - r_prev, r_prev);
        r_prev = rn;
        hout[(size_t)t * NH] = rn;            // publish slice element

        __syncthreads();                      // all STGs of this CTA's slice done
        if (tid == 0)
            asm volatile("st.release.gpu.global.s32 [%0], %1;"
                         :: "l"(&g_flag[grp][t][slice]), "r"(ready) : "memory");
    }

    // ---- end-of-group: warp ks waits for slice ks's final flag ----
    wait_flag(&g_flag[grp][NT-1][ks], par);
    __syncthreads();

    // ================= fc epilogue =================
    // CTA covers its group's 16 rows, t in [slice*64, slice*64+64).
    float* fw = smem_f;                       // reuse smem (psum dead)
    for (int i = tid; i < NC * NH; i += THREADS) fw[i] = fcW[i];
    const float fb0 = fcb[0], fb1 = fcb[1], fb2 = fcb[2];
    __syncthreads();

    float4 fw0[4], fw1[4], fw2[4];
    #pragma unroll
    for (int j = 0; j < 4; ++j) {
        const int i = hh + j * 32;
        fw0[j] = ((const float4*)(fw + 0 * NH))[i];
        fw1[j] = ((const float4*)(fw + 1 * NH))[i];
        fw2[j] = ((const float4*)(fw + 2 * NH))[i];
    }

    const int w  = tid >> 5;                  // warp = batch row in group
    const int t0 = slice * (NT / NSLICE);
    const float* hp = hidden + ((size_t)(gb + w) * NT + t0) * NH;
    float*       op = out    + ((size_t)(gb + w) * NT + t0) * NC;

    for (int it = 0; it < NT / NSLICE; ++it) {
        const float4* h4 = (const float4*)(hp + (size_t)it * NH);
        float a0 = 0.f, a1 = 0.f, a2 = 0.f;
        #pragma unroll
        for (int j = 0; j < 4; ++j) {
            float4 h = h4[hh + j * 32];
            a0 += h.x*fw0[j].x + h.y*fw0[j].y + h.z*fw0[j].z + h.w*fw0[j].w;
            a1 += h.x*fw1[j].x + h.y*fw1[j].y + h.z*fw1[j].z + h.w*fw1[j].w;
            a2 += h.x*fw2[j].x + h.y*fw2[j].y + h.z*fw2[j].z + h.w*fw2[j].w;
        }
        #pragma unroll
        for (int o = 16; o; o >>= 1) {
            a0 += __shfl_down_sync(0xffffffffu, a0, o);
            a1 += __shfl_down_sync(0xffffffffu, a1, o);
            a2 += __shfl_down_sync(0xffffffffu, a2, o);
        }
        if (hh == 0) {
            op[it*3+0] = a0 + fb0;
            op[it*3+1] = a1 + fb1;
            op[it*3+2] = a2 + fb2;
        }
    }
}

extern "C" void kernel_launch(void* const* d_in, const int* in_sizes, int n_in,
                              void* d_out, int out_size)
{
    const float* inputs = (const float*)d_in[0];
    const float* Wv     = (const float*)d_in[1];
    const float* Pv     = (const float*)d_in[2];
    const float* b_v    = (const float*)d_in[3];
    const float* Wz     = (const float*)d_in[4];
    const float* Pz     = (const float*)d_in[5];
    const float* b_z    = (const float*)d_in[6];
    const float* fcW    = (const float*)d_in[7];
    const float* fcb    = (const float*)d_in[8];

    // outputs concatenated in reference return order: out (B,T,C) then hidden (B,T,H)
    float* out    = (float*)d_out;
    float* hidden = out + (size_t)NB * NT * NC;

    const int smem_bytes = BGr * NKS * HS * 8;   // 64 KB psum
    cudaFuncSetAttribute(flipflop_main,
                         cudaFuncAttributeMaxDynamicSharedMemorySize, smem_bytes);

    flipflop_main<<<NGRP * NSLICE, THREADS, smem_bytes>>>(
        inputs, Wv, Pv, b_v, Wz, Pz, b_z, fcW, fcb, out, hidden);
}

// round 8
// speedup vs baseline: 1.4409x; 1.4409x over previous
#include <cuda_runtime.h>

#define NB 128
#define NT 1024
#define ND 3
#define NH 512
#define NC 3
#define NSLICE 16      // h-slices per batch group = CTAs per group
#define HS 32          // h per slice
#define NGRP 8         // batch groups
#define BGr 16         // batch rows per group
#define KS 32          // k per k-slice (per warp)
#define NKS 16         // k-slices = warps
#define THREADS 512

typedef unsigned long long u64;

// dataflow flags: flag[g][t][j] flips parity when group g's slice j of step t
// is published. Zero-initialized; every launch flips every slot exactly once,
// so pre-launch parity is uniform and can be probed from any slot that is
// provably not yet re-written this launch (we probe t = NT-1).
__device__ int g_flag[NGRP][NT][NSLICE];

static __device__ __forceinline__ u64 pack2(float x, float y) {
    u64 v; asm("mov.b64 %0, {%1, %2};" : "=l"(v) : "f"(x), "f"(y)); return v;
}
static __device__ __forceinline__ float2 unpack2(u64 v) {
    float2 f; asm("mov.b64 {%0, %1}, %2;" : "=f"(f.x), "=f"(f.y) : "l"(v)); return f;
}
static __device__ __forceinline__ u64 ffma2(u64 a, u64 b, u64 c) {
    u64 d; asm("fma.rn.f32x2 %0, %1, %2, %3;" : "=l"(d) : "l"(a), "l"(b), "l"(c)); return d;
}
static __device__ __forceinline__ u64 fadd2(u64 a, u64 b) {
    u64 d; asm("add.rn.f32x2 %0, %1, %2;" : "=l"(d) : "l"(a), "l"(b)); return d;
}

// all lanes poll (uniform address -> 1 sector); acquire orders the
// subsequent LDGs of the published slice.
static __device__ __forceinline__ void wait_flag(const int* pf, int stale) {
    int v;
    do {
        asm volatile("ld.acquire.gpu.global.s32 %0, [%1];"
                     : "=r"(v) : "l"(pf) : "memory");
    } while (v == stale);
}

extern __shared__ float smem_f[];

// One persistent kernel, grid 128 = 8 groups x 16 slices, 1 CTA/SM.
// compute role: warp ks consumes k-block ks (= slice ks of r(t-1)) for all 16
//               rows; it alone waits on CTA ks's flag and stages that 2KB.
// reduce  role: warp rb (= same warp index) owns batch row rb, lane hh owns
//               h = slice*32+hh; writes rn to hidden AND to rW[slice] (so the
//               own-slice consumer warp never touches global).
__global__ void __launch_bounds__(THREADS, 1)
flipflop_main(const float* __restrict__ inputs,
              const float* __restrict__ Wv,
              const float* __restrict__ Pv,
              const float* __restrict__ bv,
              const float* __restrict__ Wz,
              const float* __restrict__ Pz,
              const float* __restrict__ bz,
              const float* __restrict__ fcW,
              const float* __restrict__ fcb,
              float* __restrict__ out,
              float* __restrict__ hidden)
{
    float* rW   = smem_f;                     // [NKS][BGr][HS]  32 KB staging
    u64*   psum = (u64*)(smem_f + NKS * BGr * HS);   // [BGr][NKS][HS] 64 KB

    const int tid   = threadIdx.x;
    const int grp   = blockIdx.x >> 4;
    const int slice = blockIdx.x & 15;
    const int ks    = tid >> 5;               // warp id = k-block = reduce row
    const int hh    = tid & 31;
    const int hg    = slice * HS + hh;        // global h for this lane
    const int gb    = grp * BGr;

    // ---- weight slice into registers: k-pairs, z and v separate ----
    u64 wz[16], wv[16];
    {
        const u64* zr = (const u64*)(Wz + (size_t)hg * NH + ks * KS);
        const u64* vr = (const u64*)(Wv + (size_t)hg * NH + ks * KS);
        #pragma unroll
        for (int j = 0; j < 16; ++j) { wz[j] = zr[j]; wv[j] = vr[j]; }
    }

    // pre-launch parity probe (slot written only at the very end of a launch;
    // CTAs are pipeline-coupled within +-1 step, so no race with this launch).
    int par;
    asm volatile("ld.relaxed.gpu.global.s32 %0, [%1];"
                 : "=r"(par) : "l"(&g_flag[grp][NT-1][ks]));
    const int ready = par ^ 1;

    // ---- reduce-role constants ----
    const int rb = ks;                        // reduce row = warp index
    const float pz0 = Pz[hg*3+0], pz1 = Pz[hg*3+1], pz2 = Pz[hg*3+2];
    float pm0 = 0.f, pm1 = 0.f, pm2 = 0.f;    // P_m: bottom half zeroed
    if (hg < NH/2) { pm0 = Pv[hg*3+0]; pm1 = Pv[hg*3+1]; pm2 = Pv[hg*3+2]; }
    const float bzr = bz[hg];
    const float bvr = bv[hg];

    const float* xrow = inputs + (size_t)(gb + rb) * NT * ND;
    float*       hout = hidden + ((size_t)(gb + rb) * NT) * NH + hg;

    // staging-role constants: lane hh covers (row = hh>>3, 16B chunk = hh&7),
    // 4 iterations of 4-row stride -> 16 rows x 128B = 2KB slice.
    const int   srow  = hh >> 3;
    const int   ch4   = (hh & 7) * 4;
    const float* sbase = hidden + ((size_t)(gb + srow) * NT) * NH + ks * KS + ch4;
    float*       sdst  = rW + (ks * BGr + srow) * HS + ch4;
    const size_t sstep = (size_t)4 * NT * NH;     // 4-row stride in floats

    float* rWk = rW + ks * BGr * HS;          // this warp's compute strip

    // zero staging (r0 = 0)
    for (int i = tid; i < NKS * BGr * HS; i += THREADS) rW[i] = 0.f;
    __syncthreads();

    float r_prev = 0.f;                       // r(t-1)[rb][hg]

    for (int t = 0; t < NT; ++t) {
        const float x0 = xrow[t*3+0], x1 = xrow[t*3+1], x2 = xrow[t*3+2];

        if (t > 0) {
            // ---- per-warp dataflow: wait own k-block's producer, stage 2KB ----
            if (ks != slice) {
                wait_flag(&g_flag[grp][t-1][ks], par);
                const float* s = sbase + (size_t)(t - 1) * NH;
                #pragma unroll
                for (int j = 0; j < 4; ++j)
                    *(float4*)(sdst + j * 4 * HS) =
                        *(const float4*)(s + j * sstep);
            }
            __syncwarp();

            // ---- compute: partial (z,v) dot-products, smem broadcast ----
            #pragma unroll 1
            for (int b = 0; b < BGr; ++b) {
                const ulonglong2* rp = (const ulonglong2*)(rWk + b * HS);
                u64 az0 = 0ull, az1 = 0ull, av0 = 0ull, av1 = 0ull;
                #pragma unroll
                for (int kk = 0; kk < 8; ++kk) {
                    ulonglong2 q = rp[kk];
                    az0 = ffma2(q.x, wz[kk*2+0], az0);
                    av0 = ffma2(q.x, wv[kk*2+0], av0);
                    az1 = ffma2(q.y, wz[kk*2+1], az1);
                    av1 = ffma2(q.y, wv[kk*2+1], av1);
                }
                const float2 fz = unpack2(fadd2(az0, az1));
                const float2 fv = unpack2(fadd2(av0, av1));
                psum[(b * NKS + ks) * HS + hh] = pack2(fz.x + fz.y, fv.x + fv.y);
            }
        }
        __syncthreads();                      // psum complete

        // ---- reduce + gates: thread owns (rb, hg) ----
        float sz = 0.f, sv = 0.f;
        if (t > 0) {
            #pragma unroll
            for (int k = 0; k < NKS; ++k) {
                float2 p = unpack2(psum[(rb * NKS + k) * HS + hh]);
                sz += p.x; sv += p.y;
            }
        }
        const float az = sz + x0*pz0 + x1*pz1 + x2*pz2 + bzr;
        const float av = sv + x0*pm0 + x1*pm1 + x2*pm2 + bvr;
        const float z  = 1.f / (1.f + __expf(-az));
        const float c  = 1.f / (1.f + __expf(-av));
        const float rn = fmaf(z, c - r_prev, r_prev);
        r_prev = rn;
        hout[(size_t)t * NH] = rn;                     // publish to consumers
        rW[(slice * BGr + rb) * HS + hh] = rn;         // own-slice fast path

        __syncthreads();                      // STGs + own-slice STS done
        if (tid == 0)
            asm volatile("st.release.gpu.global.s32 [%0], %1;"
                         :: "l"(&g_flag[grp][t][slice]), "r"(ready) : "memory");
    }

    // ---- before fc: make sure every slice of this group fully published ----
    if (ks != slice) wait_flag(&g_flag[grp][NT-1][ks], par);
    __syncthreads();

    // ================= fc epilogue =================
    // CTA covers its group's 16 rows, t in [slice*64, slice*64+64).
    float* fw = (float*)psum;                 // reuse smem
    for (int i = tid; i < NC * NH; i += THREADS) fw[i] = fcW[i];
    const float fb0 = fcb[0], fb1 = fcb[1], fb2 = fcb[2];
    __syncthreads();

    float4 fw0[4], fw1[4], fw2[4];
    #pragma unroll
    for (int j = 0; j < 4; ++j) {
        const int i = hh + j * 32;
        fw0[j] = ((const float4*)(fw + 0 * NH))[i];
        fw1[j] = ((const float4*)(fw + 1 * NH))[i];
        fw2[j] = ((const float4*)(fw + 2 * NH))[i];
    }

    const int w  = tid >> 5;                  // warp = batch row in group
    const int t0 = slice * (NT / NSLICE);
    const float* hp = hidden + ((size_t)(gb + w) * NT + t0) * NH;
    float*       op = out    + ((size_t)(gb + w) * NT + t0) * NC;

    for (int it = 0; it < NT / NSLICE; ++it) {
        const float4* h4 = (const float4*)(hp + (size_t)it * NH);
        float a0 = 0.f, a1 = 0.f, a2 = 0.f;
        #pragma unroll
        for (int j = 0; j < 4; ++j) {
            float4 h = h4[hh + j * 32];
            a0 += h.x*fw0[j].x + h.y*fw0[j].y + h.z*fw0[j].z + h.w*fw0[j].w;
            a1 += h.x*fw1[j].x + h.y*fw1[j].y + h.z*fw1[j].z + h.w*fw1[j].w;
            a2 += h.x*fw2[j].x + h.y*fw2[j].y + h.z*fw2[j].z + h.w*fw2[j].w;
        }
        #pragma unroll
        for (int o = 16; o; o >>= 1) {
            a0 += __shfl_down_sync(0xffffffffu, a0, o);
            a1 += __shfl_down_sync(0xffffffffu, a1, o);
            a2 += __shfl_down_sync(0xffffffffu, a2, o);
        }
        if (hh == 0) {
            op[it*3+0] = a0 + fb0;
            op[it*3+1] = a1 + fb1;
            op[it*3+2] = a2 + fb2;
        }
    }
}

extern "C" void kernel_launch(void* const* d_in, const int* in_sizes, int n_in,
                              void* d_out, int out_size)
{
    const float* inputs = (const float*)d_in[0];
    const float* Wv     = (const float*)d_in[1];
    const float* Pv     = (const float*)d_in[2];
    const float* b_v    = (const float*)d_in[3];
    const float* Wz     = (const float*)d_in[4];
    const float* Pz     = (const float*)d_in[5];
    const float* b_z    = (const float*)d_in[6];
    const float* fcW    = (const float*)d_in[7];
    const float* fcb    = (const float*)d_in[8];

    // outputs concatenated in reference return order: out (B,T,C) then hidden (B,T,H)
    float* out    = (float*)d_out;
    float* hidden = out + (size_t)NB * NT * NC;

    const int smem_bytes = NKS * BGr * HS * 4 + BGr * NKS * HS * 8;  // 32KB + 64KB
    cudaFuncSetAttribute(flipflop_main,
                         cudaFuncAttributeMaxDynamicSharedMemorySize, smem_bytes);

    flipflop_main<<<NGRP * NSLICE, THREADS, smem_bytes>>>(
        inputs, Wv, Pv, b_v, Wz, Pz, b_z, fcW, fcb, out, hidden);
}

// round 10
// speedup vs baseline: 1.7638x; 1.2240x over previous
#include <cuda_runtime.h>

#define NB 128
#define NT 1024
#define ND 3
#define NH 512
#define NC 3
#define NSLICE 16      // h-slices per batch group = CTAs per group
#define HS 32          // h per slice
#define NGRP 8         // batch groups
#define BGr 16         // batch rows per group
#define THREADS 512
#define RSTRIDE 516    // rW row stride in words (pad -> conflict-free A loads)
#define PSTRIDE 34     // psum row stride in words (even -> v2 align, no conflicts)

typedef unsigned int u32;

// dataflow flags: flag[g][t][j] flips parity when group g's slice j of step t
// is published. Zero-initialized; every launch flips every slot exactly once,
// so pre-launch parity is uniform (probe a slot rewritten only at launch end).
__device__ int g_flag[NGRP][NT][NSLICE];

static __device__ __forceinline__ void wait_flag(const int* pf, int stale) {
    int v;
    do {
        asm volatile("ld.acquire.gpu.global.s32 %0, [%1];"
                     : "=r"(v) : "l"(pf) : "memory");
    } while (v == stale);
}
static __device__ __forceinline__ u32 to_tf32(float f) {
    u32 o; asm("cvt.rna.tf32.f32 %0, %1;" : "=r"(o) : "f"(f)); return o;
}
static __device__ __forceinline__ void mma_tf32(
    float& c0, float& c1, float& c2, float& c3,
    u32 a0, u32 a1, u32 a2, u32 a3, u32 b0, u32 b1)
{
    asm volatile(
        "mma.sync.aligned.m16n8k8.row.col.f32.tf32.tf32.f32 "
        "{%0,%1,%2,%3}, {%4,%5,%6,%7}, {%8,%9}, {%0,%1,%2,%3};"
        : "+f"(c0), "+f"(c1), "+f"(c2), "+f"(c3)
        : "r"(a0), "r"(a1), "r"(a2), "r"(a3), "r"(b0), "r"(b1));
}

extern __shared__ float smem_f[];

// One persistent kernel, grid 128 = 8 groups x 16 slices, 1 CTA/SM.
// Warp w: compute role (hq = w>>2 -> n-tile of 8 h, kq = w&3 -> 128 k);
//         stage role: rows [hq*4, hq*4+4) of its kq's 128 k (those come from
//         producer slices 4kq..4kq+3 -> polls those 4 flags), synced among the
//         4 warps of the kq quad by named barrier kq+1;
//         reduce role: batch row w, lane hh owns h = slice*32 + hh.
__global__ void __launch_bounds__(THREADS, 1)
flipflop_main(const float* __restrict__ inputs,
              const float* __restrict__ Wv,
              const float* __restrict__ Pv,
              const float* __restrict__ bv,
              const float* __restrict__ Wz,
              const float* __restrict__ Pz,
              const float* __restrict__ bz,
              const float* __restrict__ fcW,
              const float* __restrict__ fcb,
              float* __restrict__ out,
              float* __restrict__ hidden)
{
    u32*   rW   = (u32*)smem_f;               // [BGr][RSTRIDE] tf32 bits, 33 KB
    float* psum = smem_f + BGr * RSTRIDE;     // [4kq][2mat][BGr][PSTRIDE], 17 KB

    const int tid   = threadIdx.x;
    const int grp   = blockIdx.x >> 4;
    const int slice = blockIdx.x & 15;
    const int w     = tid >> 5;               // warp
    const int lane  = tid & 31;
    const int hq    = w >> 2;                 // n-tile (8 h)
    const int kq    = w & 3;                  // k-quarter (128 k)
    const int g     = lane >> 2;              // mma group id
    const int t4    = lane & 3;               // mma thread-in-group
    const int hh    = lane;                   // reduce-role h within slice
    const int hg    = slice * HS + hh;
    const int gb    = grp * BGr;

    // ---- B fragments (weights) in registers, tf32-rounded, 64 regs ----
    // b0[kb]: (k = kq*128 + kb*8 + t4,   n -> h = slice*32 + hq*8 + g)
    // b1[kb]: (k = ... + t4 + 4,         same h)
    u32 bz0[16], bz1[16], bv0[16], bv1[16];
    {
        const int hB = slice * HS + hq * 8 + g;
        const float* zrow = Wz + (size_t)hB * NH + kq * 128 + t4;
        const float* vrow = Wv + (size_t)hB * NH + kq * 128 + t4;
        #pragma unroll
        for (int kb = 0; kb < 16; ++kb) {
            bz0[kb] = to_tf32(zrow[kb*8]);
            bz1[kb] = to_tf32(zrow[kb*8 + 4]);
            bv0[kb] = to_tf32(vrow[kb*8]);
            bv1[kb] = to_tf32(vrow[kb*8 + 4]);
        }
    }

    // pre-launch parity probe (slot rewritten only at the very end of a launch)
    int par;
    asm volatile("ld.relaxed.gpu.global.s32 %0, [%1];"
                 : "=r"(par) : "l"(&g_flag[grp][NT-1][slice]));
    const int ready = par ^ 1;

    // ---- reduce-role constants (row = w) ----
    const float pz0 = Pz[hg*3+0], pz1 = Pz[hg*3+1], pz2 = Pz[hg*3+2];
    float pm0 = 0.f, pm1 = 0.f, pm2 = 0.f;    // P_m: bottom half zeroed
    if (hg < NH/2) { pm0 = Pv[hg*3+0]; pm1 = Pv[hg*3+1]; pm2 = Pv[hg*3+2]; }
    const float bzr = bz[hg];
    const float bvr = bv[hg];
    const float* xrow = inputs + (size_t)(gb + w) * NT * ND;
    float*       hout = hidden + ((size_t)(gb + w) * NT) * NH + hg;

    // ---- stage-role constants: lane covers (row = hq*4 + lane>>3,
    //      16B k-chunk = (lane&7)*4) and iterates 4 windows of 32 k. ----
    const int   srow  = hq * 4 + (lane >> 3);         // row in [0,16)
    const int   sch   = (lane & 7) * 4;               // k-chunk within a window
    const float* sgbase = hidden + ((size_t)(gb + srow) * NT) * NH + kq * 128 + sch;
    u32*        sdst  = rW + srow * RSTRIDE + kq * 128 + sch;

    // ---- A-frag base indices ----
    const int ab0 = g * RSTRIDE + t4;                 // row g,   k t4
    const int ab1 = (g + 8) * RSTRIDE + t4;           // row g+8, k t4
    const int koff0 = kq * 128;

    // ---- psum store pointers (C-frag layout) ----
    float* ps_z = psum + ((kq * 2 + 0) * BGr + g) * PSTRIDE + hq * 8 + t4 * 2;
    float* ps_v = psum + ((kq * 2 + 1) * BGr + g) * PSTRIDE + hq * 8 + t4 * 2;

    float r_prev = 0.f;                       // r(t-1)[row=w][hg]

    for (int t = 0; t < NT; ++t) {
        const float x0 = xrow[t*3+0], x1 = xrow[t*3+1], x2 = xrow[t*3+2];

        if (t > 0) {
            // ---- stage: wait this kq's 4 producer slices, copy + cvt ----
            #pragma unroll
            for (int s = 0; s < 4; ++s)
                wait_flag(&g_flag[grp][t-1][kq*4 + s], par);
            {
                const float* sg = sgbase + (size_t)(t - 1) * NH;
                #pragma unroll
                for (int j = 0; j < 4; ++j) {             // windows of 32 k
                    const float4 v = *(const float4*)(sg + j * 32);
                    uint4 o;
                    o.x = to_tf32(v.x);
                    o.y = to_tf32(v.y);
                    o.z = to_tf32(v.z);
                    o.w = to_tf32(v.w);
                    *(uint4*)(sdst + j * 32) = o;
                }
            }
            asm volatile("bar.sync %0, 128;" :: "r"(kq + 1) : "memory");

            // ---- mma: 16 k8-blocks, z and v interleaved ----
            float cz0 = 0.f, cz1 = 0.f, cz2 = 0.f, cz3 = 0.f;
            float cv0 = 0.f, cv1 = 0.f, cv2 = 0.f, cv3 = 0.f;
            #pragma unroll
            for (int kb = 0; kb < 16; ++kb) {
                const int ko = koff0 + kb * 8;
                u32 a0 = rW[ab0 + ko];
                u32 a1 = rW[ab1 + ko];
                u32 a2 = rW[ab0 + ko + 4];
                u32 a3 = rW[ab1 + ko + 4];
                mma_tf32(cz0, cz1, cz2, cz3, a0, a1, a2, a3, bz0[kb], bz1[kb]);
                mma_tf32(cv0, cv1, cv2, cv3, a0, a1, a2, a3, bv0[kb], bv1[kb]);
            }
            *(float2*)(ps_z)               = make_float2(cz0, cz1);
            *(float2*)(ps_z + 8 * PSTRIDE) = make_float2(cz2, cz3);
            *(float2*)(ps_v)               = make_float2(cv0, cv1);
            *(float2*)(ps_v + 8 * PSTRIDE) = make_float2(cv2, cv3);
        }
        __syncthreads();                      // psum complete

        // ---- reduce + gates: warp w owns row w, lane hh owns h ----
        float sz = 0.f, sv = 0.f;
        if (t > 0) {
            #pragma unroll
            for (int q = 0; q < 4; ++q) {
                sz += psum[((q * 2 + 0) * BGr + w) * PSTRIDE + hh];
                sv += psum[((q * 2 + 1) * BGr + w) * PSTRIDE + hh];
            }
        }
        const float az = sz + x0*pz0 + x1*pz1 + x2*pz2 + bzr;
        const float av = sv + x0*pm0 + x1*pm1 + x2*pm2 + bvr;
        const float z  = 1.f / (1.f + __expf(-az));
        const float c  = 1.f / (1.f + __expf(-av));
        const float rn = fmaf(z, c - r_prev, r_prev);
        r_prev = rn;
        hout[(size_t)t * NH] = rn;            // publish (fp32)

        __syncthreads();                      // all STGs of this CTA done
        if (tid == 0)
            asm volatile("st.release.gpu.global.s32 [%0], %1;"
                         :: "l"(&g_flag[grp][t][slice]), "r"(ready) : "memory");
    }

    // ensure the whole group's hidden is final before fc
    #pragma unroll
    for (int s = 0; s < 4; ++s)
        wait_flag(&g_flag[grp][NT-1][kq*4 + s], par);
    __syncthreads();

    // ================= fc epilogue =================
    float* fw = smem_f;                       // reuse smem
    for (int i = tid; i < NC * NH; i += THREADS) fw[i] = fcW[i];
    const float fb0 = fcb[0], fb1 = fcb[1], fb2 = fcb[2];
    __syncthreads();

    float4 fw0[4], fw1[4], fw2[4];
    #pragma unroll
    for (int j = 0; j < 4; ++j) {
        const int i = hh + j * 32;
        fw0[j] = ((const float4*)(fw + 0 * NH))[i];
        fw1[j] = ((const float4*)(fw + 1 * NH))[i];
        fw2[j] = ((const float4*)(fw + 2 * NH))[i];
    }

    const int t0 = slice * (NT / NSLICE);
    const float* hp = hidden + ((size_t)(gb + w) * NT + t0) * NH;
    float*       op = out    + ((size_t)(gb + w) * NT + t0) * NC;

    for (int it = 0; it < NT / NSLICE; ++it) {
        const float4* h4 = (const float4*)(hp + (size_t)it * NH);
        float a0 = 0.f, a1 = 0.f, a2 = 0.f;
        #pragma unroll
        for (int j = 0; j < 4; ++j) {
            float4 h = h4[hh + j * 32];
            a0 += h.x*fw0[j].x + h.y*fw0[j].y + h.z*fw0[j].z + h.w*fw0[j].w;
            a1 += h.x*fw1[j].x + h.y*fw1[j].y + h.z*fw1[j].z + h.w*fw1[j].w;
            a2 += h.x*fw2[j].x + h.y*fw2[j].y + h.z*fw2[j].z + h.w*fw2[j].w;
        }
        #pragma unroll
        for (int o = 16; o; o >>= 1) {
            a0 += __shfl_down_sync(0xffffffffu, a0, o);
            a1 += __shfl_down_sync(0xffffffffu, a1, o);
            a2 += __shfl_down_sync(0xffffffffu, a2, o);
        }
        if (hh == 0) {
            op[it*3+0] = a0 + fb0;
            op[it*3+1] = a1 + fb1;
            op[it*3+2] = a2 + fb2;
        }
    }
}

extern "C" void kernel_launch(void* const* d_in, const int* in_sizes, int n_in,
                              void* d_out, int out_size)
{
    const float* inputs = (const float*)d_in[0];
    const float* Wv     = (const float*)d_in[1];
    const float* Pv     = (const float*)d_in[2];
    const float* b_v    = (const float*)d_in[3];
    const float* Wz     = (const float*)d_in[4];
    const float* Pz     = (const float*)d_in[5];
    const float* b_z    = (const float*)d_in[6];
    const float* fcW    = (const float*)d_in[7];
    const float* fcb    = (const float*)d_in[8];

    // outputs concatenated in reference return order: out (B,T,C) then hidden (B,T,H)
    float* out    = (float*)d_out;
    float* hidden = out + (size_t)NB * NT * NC;

    const int smem_bytes = (BGr * RSTRIDE + 4 * 2 * BGr * PSTRIDE) * 4;
    cudaFuncSetAttribute(flipflop_main,
                         cudaFuncAttributeMaxDynamicSharedMemorySize, smem_bytes);

    flipflop_main<<<NGRP * NSLICE, THREADS, smem_bytes>>>(
        inputs, Wv, Pv, b_v, Wz, Pz, b_z, fcW, fcb, out, hidden);
}

// round 11
// speedup vs baseline: 2.0558x; 1.1656x over previous
#include <cuda_runtime.h>

#define NB 128
#define NT 1024
#define ND 3
#define NH 512
#define NC 3
#define NSLICE 16      // h-slices per batch group = CTAs per group
#define HS 32          // h per slice
#define NGRP 16        // batch groups (8 rows); each CTA serves 2 groups
#define BGr 8          // batch rows per group
#define THREADS 512
#define RSTRIDE 516    // rW row stride in words (pad -> conflict-free A loads)
#define PSTRIDE 34     // psum row stride in words

typedef unsigned int u32;

// dataflow flags, t fastest: pollers of different slices hit different L2
// lines (the R4..R9 layouts put all 16 slices of a step on ONE line ->
// ~256 concurrent pollers serialized on a single LTS slice).
// Zero-initialized; every slot flips parity exactly once per launch, so
// pre-launch parity is uniform; each CTA probes its OWN slot [g][slice][NT-1]
// (written only by itself at the very end of a launch -> race-free).
__device__ int g_flag[NGRP][NSLICE][NT];

static __device__ __forceinline__ void wait_flag(const int* pf, int stale) {
    int v;
    do {
        asm volatile("ld.acquire.gpu.global.s32 %0, [%1];"
                     : "=r"(v) : "l"(pf) : "memory");
    } while (v == stale);
}
static __device__ __forceinline__ u32 to_tf32(float f) {
    u32 o; asm("cvt.rna.tf32.f32 %0, %1;" : "=r"(o) : "f"(f)); return o;
}
static __device__ __forceinline__ void mma_tf32(
    float& c0, float& c1, float& c2, float& c3,
    u32 a0, u32 a1, u32 a2, u32 a3, u32 b0, u32 b1)
{
    asm volatile(
        "mma.sync.aligned.m16n8k8.row.col.f32.tf32.tf32.f32 "
        "{%0,%1,%2,%3}, {%4,%5,%6,%7}, {%8,%9}, {%0,%1,%2,%3};"
        : "+f"(c0), "+f"(c1), "+f"(c2), "+f"(c3)
        : "r"(a0), "r"(a1), "r"(a2), "r"(a3), "r"(b0), "r"(b1));
}

extern __shared__ float smem_f[];

// Grid 128 = 8 pairs x 16 slices, 1 CTA/SM. CTA (pair, slice) serves groups
// gA=2*pair, gB=2*pair+1 (8 batch rows each), alternating phases so group A's
// flag/data propagation is hidden behind group B's compute and vice versa.
// Warp w = hq*4+kq: mma tile (hq -> 8 h, kq -> 128 k); quad poller = hq==2.
// Reduce role: warps 0..7 own batch row w; lane hh owns h = slice*32+hh.
__global__ void __launch_bounds__(THREADS, 1)
flipflop_main(const float* __restrict__ inputs,
              const float* __restrict__ Wv,
              const float* __restrict__ Pv,
              const float* __restrict__ bv,
              const float* __restrict__ Wz,
              const float* __restrict__ Pz,
              const float* __restrict__ bz,
              const float* __restrict__ fcW,
              const float* __restrict__ fcb,
              float* __restrict__ out,
              float* __restrict__ hidden)
{
    u32*   rWA = (u32*)smem_f;                    // [16][RSTRIDE] (rows 8-15 zero)
    u32*   rWB = rWA + 16 * RSTRIDE;
    float* psA = (float*)(rWB + 16 * RSTRIDE);    // [4kq][2][BGr][PSTRIDE]
    float* psB = psA + 4 * 2 * BGr * PSTRIDE;

    const int tid   = threadIdx.x;
    const int pair  = blockIdx.x >> 4;
    const int slice = blockIdx.x & 15;
    const int gA    = pair * 2, gB = gA + 1;
    const int gbA   = gA * BGr, gbB = gB * BGr;
    const int w     = tid >> 5;
    const int lane  = tid & 31;
    const int hq    = w >> 2;
    const int kq    = w & 3;
    const int g     = lane >> 2;
    const int t4    = lane & 3;
    const int hh    = lane;
    const int hg    = slice * HS + hh;

    // ---- B fragments (weights) in registers, tf32, 64 regs ----
    u32 bz0[16], bz1[16], bv0[16], bv1[16];
    {
        const int hB = slice * HS + hq * 8 + g;
        const float* zrow = Wz + (size_t)hB * NH + kq * 128 + t4;
        const float* vrow = Wv + (size_t)hB * NH + kq * 128 + t4;
        #pragma unroll
        for (int kb = 0; kb < 16; ++kb) {
            bz0[kb] = to_tf32(zrow[kb*8]);
            bz1[kb] = to_tf32(zrow[kb*8 + 4]);
            bv0[kb] = to_tf32(vrow[kb*8]);
            bv1[kb] = to_tf32(vrow[kb*8 + 4]);
        }
    }

    // parity probes (own slots; written only by this CTA at launch end)
    int parA, parB;
    asm volatile("ld.relaxed.gpu.global.s32 %0, [%1];"
                 : "=r"(parA) : "l"(&g_flag[gA][slice][NT-1]));
    asm volatile("ld.relaxed.gpu.global.s32 %0, [%1];"
                 : "=r"(parB) : "l"(&g_flag[gB][slice][NT-1]));
    const int readyA = parA ^ 1, readyB = parB ^ 1;

    // ---- reduce-role constants (valid for w<8) ----
    const float pz0 = Pz[hg*3+0], pz1 = Pz[hg*3+1], pz2 = Pz[hg*3+2];
    float pm0 = 0.f, pm1 = 0.f, pm2 = 0.f;        // P_m: bottom half zeroed
    if (hg < NH/2) { pm0 = Pv[hg*3+0]; pm1 = Pv[hg*3+1]; pm2 = Pv[hg*3+2]; }
    const float bzr = bz[hg];
    const float bvr = bv[hg];
    const int   rrow = w & 7;                     // clamp for addr safety
    const float* xrowA = inputs + (size_t)(gbA + rrow) * NT * ND;
    const float* xrowB = inputs + (size_t)(gbB + rrow) * NT * ND;
    float* houtA = hidden + ((size_t)(gbA + rrow) * NT) * NH + hg;
    float* houtB = hidden + ((size_t)(gbB + rrow) * NT) * NH + hg;

    // ---- stage-role constants: warp stages rows [hq*2, hq*2+2) of its kq ----
    const int srow = hq * 2 + (lane >> 4);        // 0..7
    const int sf4w = (lane & 15) * 4;             // word offset in window
    const float* sgA = hidden + ((size_t)(gbA + srow) * NT) * NH + kq * 128 + sf4w;
    const float* sgB = hidden + ((size_t)(gbB + srow) * NT) * NH + kq * 128 + sf4w;
    u32* sdA = rWA + srow * RSTRIDE + kq * 128 + sf4w;
    u32* sdB = rWB + srow * RSTRIDE + kq * 128 + sf4w;

    // ---- A-frag / psum indices ----
    const int ab0 = g * RSTRIDE + t4;
    const int ab1 = (g + 8) * RSTRIDE + t4;       // rows 8-15: pinned zero
    const int koff0 = kq * 128;
    const int psz_i = ((kq * 2 + 0) * BGr + g) * PSTRIDE + hq * 8 + t4 * 2;
    const int psv_i = ((kq * 2 + 1) * BGr + g) * PSTRIDE + hq * 8 + t4 * 2;

    // zero both rW buffers (incl. junk rows) -> r0 = 0, junk rows stay 0
    for (int i = tid; i < 2 * 16 * RSTRIDE; i += THREADS) rWA[i] = 0u;
    __syncthreads();

    float rpA = 0.f, rpB = 0.f;

    for (int t = 0; t < NT; ++t) {
        float xa0=0.f, xa1=0.f, xa2=0.f, xb0=0.f, xb1=0.f, xb2=0.f;
        if (w < 8) {
            xa0 = xrowA[t*3+0]; xa1 = xrowA[t*3+1]; xa2 = xrowA[t*3+2];
            xb0 = xrowB[t*3+0]; xb1 = xrowB[t*3+1]; xb2 = xrowB[t*3+2];
        }

        // ===================== phase A =====================
        if (t > 0) {
            if (hq == 2) {                         // quad poller (non-reduce warp)
                #pragma unroll
                for (int s = 0; s < 4; ++s)
                    wait_flag(&g_flag[gA][kq*4 + s][t-1], parA);
            }
            asm volatile("bar.sync %0, 128;" :: "r"(kq + 1) : "memory");
            {   // stage A: 2 rows x 128 k per warp
                const float* s = sgA + (size_t)(t - 1) * NH;
                const float4 v0 = *(const float4*)(s);
                const float4 v1 = *(const float4*)(s + 64);
                uint4 o0, o1;
                o0.x = to_tf32(v0.x); o0.y = to_tf32(v0.y);
                o0.z = to_tf32(v0.z); o0.w = to_tf32(v0.w);
                o1.x = to_tf32(v1.x); o1.y = to_tf32(v1.y);
                o1.z = to_tf32(v1.z); o1.w = to_tf32(v1.w);
                *(uint4*)(sdA)      = o0;
                *(uint4*)(sdA + 64) = o1;
            }
            asm volatile("bar.sync %0, 128;" :: "r"(kq + 1) : "memory");

            float cz0=0.f,cz1=0.f,cz2=0.f,cz3=0.f, cv0=0.f,cv1=0.f,cv2=0.f,cv3=0.f;
            #pragma unroll
            for (int kb = 0; kb < 16; ++kb) {
                const int ko = koff0 + kb * 8;
                u32 a0 = rWA[ab0 + ko], a1 = rWA[ab1 + ko];
                u32 a2 = rWA[ab0 + ko + 4], a3 = rWA[ab1 + ko + 4];
                mma_tf32(cz0,cz1,cz2,cz3, a0,a1,a2,a3, bz0[kb],bz1[kb]);
                mma_tf32(cv0,cv1,cv2,cv3, a0,a1,a2,a3, bv0[kb],bv1[kb]);
            }
            *(float2*)(psA + psz_i) = make_float2(cz0, cz1);
            *(float2*)(psA + psv_i) = make_float2(cv0, cv1);
        }
        __syncthreads();
        if (w < 8) {
            float sz = 0.f, sv = 0.f;
            if (t > 0) {
                #pragma unroll
                for (int q = 0; q < 4; ++q) {
                    sz += psA[((q*2 + 0) * BGr + w) * PSTRIDE + hh];
                    sv += psA[((q*2 + 1) * BGr + w) * PSTRIDE + hh];
                }
            }
            const float az = sz + xa0*pz0 + xa1*pz1 + xa2*pz2 + bzr;
            const float av = sv + xa0*pm0 + xa1*pm1 + xa2*pm2 + bvr;
            const float z  = 1.f / (1.f + __expf(-az));
            const float c  = 1.f / (1.f + __expf(-av));
            const float rn = fmaf(z, c - rpA, rpA);
            rpA = rn;
            houtA[(size_t)t * NH] = rn;
            asm volatile("bar.sync 5, 256;" ::: "memory");   // warps 0-7 only
            if (tid == 0)
                asm volatile("st.release.gpu.global.s32 [%0], %1;"
                             :: "l"(&g_flag[gA][slice][t]), "r"(readyA) : "memory");
        }

        // ===================== phase B =====================
        if (t > 0) {
            if (hq == 2) {
                #pragma unroll
                for (int s = 0; s < 4; ++s)
                    wait_flag(&g_flag[gB][kq*4 + s][t-1], parB);
            }
            asm volatile("bar.sync %0, 128;" :: "r"(kq + 1) : "memory");
            {
                const float* s = sgB + (size_t)(t - 1) * NH;
                const float4 v0 = *(const float4*)(s);
                const float4 v1 = *(const float4*)(s + 64);
                uint4 o0, o1;
                o0.x = to_tf32(v0.x); o0.y = to_tf32(v0.y);
                o0.z = to_tf32(v0.z); o0.w = to_tf32(v0.w);
                o1.x = to_tf32(v1.x); o1.y = to_tf32(v1.y);
                o1.z = to_tf32(v1.z); o1.w = to_tf32(v1.w);
                *(uint4*)(sdB)      = o0;
                *(uint4*)(sdB + 64) = o1;
            }
            asm volatile("bar.sync %0, 128;" :: "r"(kq + 1) : "memory");

            float cz0=0.f,cz1=0.f,cz2=0.f,cz3=0.f, cv0=0.f,cv1=0.f,cv2=0.f,cv3=0.f;
            #pragma unroll
            for (int kb = 0; kb < 16; ++kb) {
                const int ko = koff0 + kb * 8;
                u32 a0 = rWB[ab0 + ko], a1 = rWB[ab1 + ko];
                u32 a2 = rWB[ab0 + ko + 4], a3 = rWB[ab1 + ko + 4];
                mma_tf32(cz0,cz1,cz2,cz3, a0,a1,a2,a3, bz0[kb],bz1[kb]);
                mma_tf32(cv0,cv1,cv2,cv3, a0,a1,a2,a3, bv0[kb],bv1[kb]);
            }
            *(float2*)(psB + psz_i) = make_float2(cz0, cz1);
            *(float2*)(psB + psv_i) = make_float2(cv0, cv1);
        }
        __syncthreads();
        if (w < 8) {
            float sz = 0.f, sv = 0.f;
            if (t > 0) {
                #pragma unroll
                for (int q = 0; q < 4; ++q) {
                    sz += psB[((q*2 + 0) * BGr + w) * PSTRIDE + hh];
                    sv += psB[((q*2 + 1) * BGr + w) * PSTRIDE + hh];
                }
            }
            const float az = sz + xb0*pz0 + xb1*pz1 + xb2*pz2 + bzr;
            const float av = sv + xb0*pm0 + xb1*pm1 + xb2*pm2 + bvr;
            const float z  = 1.f / (1.f + __expf(-az));
            const float c  = 1.f / (1.f + __expf(-av));
            const float rn = fmaf(z, c - rpB, rpB);
            rpB = rn;
            houtB[(size_t)t * NH] = rn;
            asm volatile("bar.sync 5, 256;" ::: "memory");
            if (tid == 0)
                asm volatile("st.release.gpu.global.s32 [%0], %1;"
                             :: "l"(&g_flag[gB][slice][t]), "r"(readyB) : "memory");
        }
    }

    // wait for all slices of both groups before fc (warp w <-> slice w)
    wait_flag(&g_flag[gA][w][NT-1], parA);
    wait_flag(&g_flag[gB][w][NT-1], parB);
    __syncthreads();

    // ================= fc epilogue =================
    float* fw = (float*)rWA;                      // reuse smem
    for (int i = tid; i < NC * NH; i += THREADS) fw[i] = fcW[i];
    const float fb0 = fcb[0], fb1 = fcb[1], fb2 = fcb[2];
    __syncthreads();

    float4 fw0[4], fw1[4], fw2[4];
    #pragma unroll
    for (int j = 0; j < 4; ++j) {
        const int i = hh + j * 32;
        fw0[j] = ((const float4*)(fw + 0 * NH))[i];
        fw1[j] = ((const float4*)(fw + 1 * NH))[i];
        fw2[j] = ((const float4*)(fw + 2 * NH))[i];
    }

    const int row = (w < 8) ? (gbA + w) : (gbB + (w - 8));
    const int t0  = slice * (NT / NSLICE);
    const float* hp = hidden + ((size_t)row * NT + t0) * NH;
    float*       op = out    + ((size_t)row * NT + t0) * NC;

    for (int it = 0; it < NT / NSLICE; ++it) {
        const float4* h4 = (const float4*)(hp + (size_t)it * NH);
        float a0 = 0.f, a1 = 0.f, a2 = 0.f;
        #pragma unroll
        for (int j = 0; j < 4; ++j) {
            float4 h = h4[hh + j * 32];
            a0 += h.x*fw0[j].x + h.y*fw0[j].y + h.z*fw0[j].z + h.w*fw0[j].w;
            a1 += h.x*fw1[j].x + h.y*fw1[j].y + h.z*fw1[j].z + h.w*fw1[j].w;
            a2 += h.x*fw2[j].x + h.y*fw2[j].y + h.z*fw2[j].z + h.w*fw2[j].w;
        }
        #pragma unroll
        for (int o = 16; o; o >>= 1) {
            a0 += __shfl_down_sync(0xffffffffu, a0, o);
            a1 += __shfl_down_sync(0xffffffffu, a1, o);
            a2 += __shfl_down_sync(0xffffffffu, a2, o);
        }
        if (hh == 0) {
            op[it*3+0] = a0 + fb0;
            op[it*3+1] = a1 + fb1;
            op[it*3+2] = a2 + fb2;
        }
    }
}

extern "C" void kernel_launch(void* const* d_in, const int* in_sizes, int n_in,
                              void* d_out, int out_size)
{
    const float* inputs = (const float*)d_in[0];
    const float* Wv     = (const float*)d_in[1];
    const float* Pv     = (const float*)d_in[2];
    const float* b_v    = (const float*)d_in[3];
    const float* Wz     = (const float*)d_in[4];
    const float* Pz     = (const float*)d_in[5];
    const float* b_z    = (const float*)d_in[6];
    const float* fcW    = (const float*)d_in[7];
    const float* fcb    = (const float*)d_in[8];

    // outputs concatenated in reference return order: out (B,T,C) then hidden (B,T,H)
    float* out    = (float*)d_out;
    float* hidden = out + (size_t)NB * NT * NC;

    const int smem_bytes = (2 * 16 * RSTRIDE + 2 * 4 * 2 * BGr * PSTRIDE) * 4;
    cudaFuncSetAttribute(flipflop_main,
                         cudaFuncAttributeMaxDynamicSharedMemorySize, smem_bytes);

    flipflop_main<<<(NGRP / 2) * NSLICE, THREADS, smem_bytes>>>(
        inputs, Wv, Pv, b_v, Wz, Pz, b_z, fcW, fcb, out, hidden);
}

// round 12
// speedup vs baseline: 2.0999x; 1.0214x over previous
#include <cuda_runtime.h>

#define NB 128
#define NT 1024
#define ND 3
#define NH 512
#define NC 3
#define NSLICE 16      // h-slices per batch group = CTAs per group
#define HS 32          // h per slice
#define NGRP 16        // batch groups (8 rows); each CTA serves 2 groups
#define BGr 8          // batch rows per group
#define THREADS 512
#define RSTRIDE 516    // rW row stride in words (pad -> conflict-free A loads)
#define PSTRIDE 34     // psum row stride in words

typedef unsigned int u32;

// dataflow flags, t fastest (pollers of different slices on different L2
// lines). Zero-initialized; every slot flips parity exactly once per launch,
// so pre-launch parity is uniform; each CTA probes its OWN slot (written only
// by itself at the very end of a launch -> race-free).
__device__ int g_flag[NGRP][NSLICE][NT];

static __device__ __forceinline__ void wait_flag(const int* pf, int stale) {
    int v;
    do {
        asm volatile("ld.acquire.gpu.global.s32 %0, [%1];"
                     : "=r"(v) : "l"(pf) : "memory");
    } while (v == stale);
}
static __device__ __forceinline__ u32 to_tf32(float f) {
    u32 o; asm("cvt.rna.tf32.f32 %0, %1;" : "=r"(o) : "f"(f)); return o;
}
static __device__ __forceinline__ void mma_tf32(
    float& c0, float& c1, float& c2, float& c3,
    u32 a0, u32 a1, u32 a2, u32 a3, u32 b0, u32 b1)
{
    asm volatile(
        "mma.sync.aligned.m16n8k8.row.col.f32.tf32.tf32.f32 "
        "{%0,%1,%2,%3}, {%4,%5,%6,%7}, {%8,%9}, {%0,%1,%2,%3};"
        : "+f"(c0), "+f"(c1), "+f"(c2), "+f"(c3)
        : "r"(a0), "r"(a1), "r"(a2), "r"(a3), "r"(b0), "r"(b1));
}

extern __shared__ float smem_f[];

// Grid 128 = 8 pairs x 16 slices, 1 CTA/SM. CTA (pair, slice) serves groups
// gA=2*pair (mma rows 0-7, computing step t) and gB=2*pair+1 (mma rows 8-15,
// computing step t-1) in a SINGLE skewed mma pass per iteration. Both input
// states consumed at iteration t were published at the end of iteration t-1,
// giving a full iteration of slack for flag/data propagation.
// Warp w = hq*4+kq: mma tile (hq -> 8 h, kq -> 128 k); quad poller = hq==2.
// Stage role: warp stages rows [hq*4, hq*4+4) of its kq's 128 k.
// Reduce role: w<8 -> group A row w (step t); w>=8 -> group B row w-8 (t-1).
__global__ void __launch_bounds__(THREADS, 1)
flipflop_main(const float* __restrict__ inputs,
              const float* __restrict__ Wv,
              const float* __restrict__ Pv,
              const float* __restrict__ bv,
              const float* __restrict__ Wz,
              const float* __restrict__ Pz,
              const float* __restrict__ bz,
              const float* __restrict__ fcW,
              const float* __restrict__ fcb,
              float* __restrict__ out,
              float* __restrict__ hidden)
{
    u32*   rW = (u32*)smem_f;                 // [16][RSTRIDE]: A rows 0-7 (t-1),
                                              //               B rows 8-15 (t-2)
    float* ps = smem_f + 16 * RSTRIDE;        // [4kq][2][16rows][PSTRIDE]

    const int tid   = threadIdx.x;
    const int pair  = blockIdx.x >> 4;
    const int slice = blockIdx.x & 15;
    const int gA    = pair * 2, gB = gA + 1;
    const int gbA   = gA * BGr, gbB = gB * BGr;
    const int w     = tid >> 5;
    const int lane  = tid & 31;
    const int hq    = w >> 2;
    const int kq    = w & 3;
    const int g     = lane >> 2;
    const int t4    = lane & 3;
    const int hh    = lane;
    const int hg    = slice * HS + hh;

    // ---- B fragments (weights) in registers, tf32, 64 regs ----
    u32 bz0[16], bz1[16], bv0[16], bv1[16];
    {
        const int hB = slice * HS + hq * 8 + g;
        const float* zrow = Wz + (size_t)hB * NH + kq * 128 + t4;
        const float* vrow = Wv + (size_t)hB * NH + kq * 128 + t4;
        #pragma unroll
        for (int kb = 0; kb < 16; ++kb) {
            bz0[kb] = to_tf32(zrow[kb*8]);
            bz1[kb] = to_tf32(zrow[kb*8 + 4]);
            bv0[kb] = to_tf32(vrow[kb*8]);
            bv1[kb] = to_tf32(vrow[kb*8 + 4]);
        }
    }

    // parity probes (own slots; rewritten only by this CTA at launch end)
    int parA, parB;
    asm volatile("ld.relaxed.gpu.global.s32 %0, [%1];"
                 : "=r"(parA) : "l"(&g_flag[gA][slice][NT-1]));
    asm volatile("ld.relaxed.gpu.global.s32 %0, [%1];"
                 : "=r"(parB) : "l"(&g_flag[gB][slice][NT-1]));
    const int readyA = parA ^ 1, readyB = parB ^ 1;

    // ---- reduce-role constants ----
    const float pz0 = Pz[hg*3+0], pz1 = Pz[hg*3+1], pz2 = Pz[hg*3+2];
    float pm0 = 0.f, pm1 = 0.f, pm2 = 0.f;        // P_m: bottom half zeroed
    if (hg < NH/2) { pm0 = Pv[hg*3+0]; pm1 = Pv[hg*3+1]; pm2 = Pv[hg*3+2]; }
    const float bzr = bz[hg];
    const float bvr = bv[hg];
    const int   rrow  = w & 7;
    const int   myrow = (w < 8) ? (gbA + rrow) : (gbB + rrow);
    const float* xrow = inputs + (size_t)myrow * NT * ND;
    float*       hout = hidden + ((size_t)myrow * NT) * NH + hg;

    // ---- stage-role: warp stages rows [hq*4, hq*4+4) of its kq columns ----
    const int  srow   = hq * 4 + (lane >> 3);     // 0..15
    const int  sch    = (lane & 7) * 4;           // word chunk within window
    const bool stA    = (srow < 8);               // rows 0-7 from group A
    const int  sgrow  = stA ? (gbA + srow) : (gbB + srow - 8);
    const float* sg   = hidden + ((size_t)sgrow * NT) * NH + kq * 128 + sch;
    u32*        sd    = rW + srow * RSTRIDE + kq * 128 + sch;

    // ---- A-frag / psum indices ----
    const int ab0 = g * RSTRIDE + t4;
    const int ab1 = (g + 8) * RSTRIDE + t4;
    const int koff0 = kq * 128;
    const int psz_i = ((kq * 2 + 0) * 16 + g) * PSTRIDE + hq * 8 + t4 * 2;
    const int psv_i = ((kq * 2 + 1) * 16 + g) * PSTRIDE + hq * 8 + t4 * 2;

    // zero rW -> r0 = 0 for both groups
    for (int i = tid; i < 16 * RSTRIDE; i += THREADS) rW[i] = 0u;
    __syncthreads();

    float r_prev = 0.f;          // w<8: r_A(t-1)[row]; w>=8: r_B(t-2)[row]

    for (int t = 0; t <= NT; ++t) {
        // prefetch this warp's x (A: step t; B: step t-1)
        float x0 = 0.f, x1 = 0.f, x2 = 0.f;
        {
            const int xs = (w < 8) ? t : (t - 1);
            if (xs >= 0 && xs < NT) {
                x0 = xrow[xs*3+0]; x1 = xrow[xs*3+1]; x2 = xrow[xs*3+2];
            }
        }

        // ---- poll: quad poller waits this kq's 8 producer flags ----
        if (hq == 2) {
            if (t >= 1 && t < NT) {
                #pragma unroll
                for (int s = 0; s < 4; ++s)
                    wait_flag(&g_flag[gA][kq*4 + s][t-1], parA);
            }
            if (t >= 2) {
                #pragma unroll
                for (int s = 0; s < 4; ++s)
                    wait_flag(&g_flag[gB][kq*4 + s][t-2], parB);
            }
        }
        asm volatile("bar.sync %0, 128;" :: "r"(kq + 1) : "memory");

        // ---- stage: A rows need r_A(t-1); B rows need r_B(t-2) ----
        if (stA ? (t >= 1 && t < NT) : (t >= 2)) {
            const float* s = sg + (size_t)(stA ? (t - 1) : (t - 2)) * NH;
            #pragma unroll
            for (int j = 0; j < 4; ++j) {                 // windows of 32 k
                const float4 v = *(const float4*)(s + j * 32);
                uint4 o;
                o.x = to_tf32(v.x); o.y = to_tf32(v.y);
                o.z = to_tf32(v.z); o.w = to_tf32(v.w);
                *(uint4*)(sd + j * 32) = o;
            }
        }
        asm volatile("bar.sync %0, 128;" :: "r"(kq + 1) : "memory");

        // ---- single mma pass: rows 0-7 = A(t), rows 8-15 = B(t-1) ----
        if (t >= 1) {
            float cz0=0.f,cz1=0.f,cz2=0.f,cz3=0.f, cv0=0.f,cv1=0.f,cv2=0.f,cv3=0.f;
            #pragma unroll
            for (int kb = 0; kb < 16; ++kb) {
                const int ko = koff0 + kb * 8;
                u32 a0 = rW[ab0 + ko], a1 = rW[ab1 + ko];
                u32 a2 = rW[ab0 + ko + 4], a3 = rW[ab1 + ko + 4];
                mma_tf32(cz0,cz1,cz2,cz3, a0,a1,a2,a3, bz0[kb],bz1[kb]);
                mma_tf32(cv0,cv1,cv2,cv3, a0,a1,a2,a3, bv0[kb],bv1[kb]);
            }
            *(float2*)(ps + psz_i)               = make_float2(cz0, cz1);
            *(float2*)(ps + psz_i + 8 * PSTRIDE) = make_float2(cz2, cz3);
            *(float2*)(ps + psv_i)               = make_float2(cv0, cv1);
            *(float2*)(ps + psv_i + 8 * PSTRIDE) = make_float2(cv2, cv3);
        }
        __syncthreads();                          // psum complete

        // ---- reduce + gates: warp w owns mma row w ----
        {
            const int xs   = (w < 8) ? t : (t - 1);      // step this warp emits
            const bool run = (xs >= 0) && (xs < NT);
            const bool hasp = (w < 8) ? (t >= 1) : (t >= 2);
            if (run) {
                float sz = 0.f, sv = 0.f;
                if (hasp) {
                    #pragma unroll
                    for (int q = 0; q < 4; ++q) {
                        sz += ps[((q*2 + 0) * 16 + w) * PSTRIDE + hh];
                        sv += ps[((q*2 + 1) * 16 + w) * PSTRIDE + hh];
                    }
                }
                const float az = sz + x0*pz0 + x1*pz1 + x2*pz2 + bzr;
                const float av = sv + x0*pm0 + x1*pm1 + x2*pm2 + bvr;
                const float z  = 1.f / (1.f + __expf(-az));
                const float c  = 1.f / (1.f + __expf(-av));
                const float rn = fmaf(z, c - r_prev, r_prev);
                r_prev = rn;
                hout[(size_t)xs * NH] = rn;
            }
        }
        __syncthreads();                          // all STGs done
        if (tid == 0) {
            if (t < NT)
                asm volatile("st.release.gpu.global.s32 [%0], %1;"
                             :: "l"(&g_flag[gA][slice][t]), "r"(readyA) : "memory");
            if (t >= 1)
                asm volatile("st.release.gpu.global.s32 [%0], %1;"
                             :: "l"(&g_flag[gB][slice][t-1]), "r"(readyB) : "memory");
        }
    }

    // wait for all slices of both groups before fc (warp w <-> slice w)
    wait_flag(&g_flag[gA][w][NT-1], parA);
    wait_flag(&g_flag[gB][w][NT-1], parB);
    __syncthreads();

    // ================= fc epilogue =================
    float* fw = smem_f;                           // reuse smem
    for (int i = tid; i < NC * NH; i += THREADS) fw[i] = fcW[i];
    const float fb0 = fcb[0], fb1 = fcb[1], fb2 = fcb[2];
    __syncthreads();

    float4 fw0[4], fw1[4], fw2[4];
    #pragma unroll
    for (int j = 0; j < 4; ++j) {
        const int i = hh + j * 32;
        fw0[j] = ((const float4*)(fw + 0 * NH))[i];
        fw1[j] = ((const float4*)(fw + 1 * NH))[i];
        fw2[j] = ((const float4*)(fw + 2 * NH))[i];
    }

    const int row = myrow;                        // same warp->row map as loop
    const int t0  = slice * (NT / NSLICE);
    const float* hp = hidden + ((size_t)row * NT + t0) * NH;
    float*       op = out    + ((size_t)row * NT + t0) * NC;

    for (int it = 0; it < NT / NSLICE; ++it) {
        const float4* h4 = (const float4*)(hp + (size_t)it * NH);
        float a0 = 0.f, a1 = 0.f, a2 = 0.f;
        #pragma unroll
        for (int j = 0; j < 4; ++j) {
            float4 h = h4[hh + j * 32];
            a0 += h.x*fw0[j].x + h.y*fw0[j].y + h.z*fw0[j].z + h.w*fw0[j].w;
            a1 += h.x*fw1[j].x + h.y*fw1[j].y + h.z*fw1[j].z + h.w*fw1[j].w;
            a2 += h.x*fw2[j].x + h.y*fw2[j].y + h.z*fw2[j].z + h.w*fw2[j].w;
        }
        #pragma unroll
        for (int o = 16; o; o >>= 1) {
            a0 += __shfl_down_sync(0xffffffffu, a0, o);
            a1 += __shfl_down_sync(0xffffffffu, a1, o);
            a2 += __shfl_down_sync(0xffffffffu, a2, o);
        }
        if (hh == 0) {
            op[it*3+0] = a0 + fb0;
            op[it*3+1] = a1 + fb1;
            op[it*3+2] = a2 + fb2;
        }
    }
}

extern "C" void kernel_launch(void* const* d_in, const int* in_sizes, int n_in,
                              void* d_out, int out_size)
{
    const float* inputs = (const float*)d_in[0];
    const float* Wv     = (const float*)d_in[1];
    const float* Pv     = (const float*)d_in[2];
    const float* b_v    = (const float*)d_in[3];
    const float* Wz     = (const float*)d_in[4];
    const float* Pz     = (const float*)d_in[5];
    const float* b_z    = (const float*)d_in[6];
    const float* fcW    = (const float*)d_in[7];
    const float* fcb    = (const float*)d_in[8];

    // outputs concatenated in reference return order: out (B,T,C) then hidden (B,T,H)
    float* out    = (float*)d_out;
    float* hidden = out + (size_t)NB * NT * NC;

    const int smem_bytes = (16 * RSTRIDE + 4 * 2 * 16 * PSTRIDE) * 4;
    cudaFuncSetAttribute(flipflop_main,
                         cudaFuncAttributeMaxDynamicSharedMemorySize, smem_bytes);

    flipflop_main<<<(NGRP / 2) * NSLICE, THREADS, smem_bytes>>>(
        inputs, Wv, Pv, b_v, Wz, Pz, b_z, fcW, fcb, out, hidden);
}

// round 13
// speedup vs baseline: 2.9455x; 1.4027x over previous
#include <cuda_runtime.h>

#define NB 128
#define NT 1024
#define ND 3
#define NH 512
#define NC 3
#define NSLICE 16      // h-slices per batch group = CTAs per group
#define HS 32          // h per slice
#define NGRP 16        // batch groups (8 rows); each CTA serves 2 groups
#define BGr 8          // batch rows per group
#define THREADS 512
#define RSTRIDE 516    // rW row stride in words (pad -> conflict-free A loads)
#define PSTRIDE 34     // psum row stride in words
#define PSUMW (4 * 2 * 16 * PSTRIDE)   // words per psum buffer

typedef unsigned int u32;

// per-(group, slice, row, t) dataflow flags (8 MB). Row-level granularity:
// each reduce warp publishes its own row; each consumer lane polls exactly
// the (slice,row) it stages -> parallel single-RT detection, no bulk sync.
// Zero-initialized; every slot flips parity exactly once per launch.
__device__ int g_flag[NGRP][NSLICE][BGr][NT];

static __device__ __forceinline__ void wait_flag(const int* pf, int stale) {
    int v;
    do {
        asm volatile("ld.acquire.gpu.global.s32 %0, [%1];"
                     : "=r"(v) : "l"(pf) : "memory");
    } while (v == stale);
}
static __device__ __forceinline__ u32 to_tf32(float f) {
    u32 o; asm("cvt.rna.tf32.f32 %0, %1;" : "=r"(o) : "f"(f)); return o;
}
static __device__ __forceinline__ void mma_tf32(
    float& c0, float& c1, float& c2, float& c3,
    u32 a0, u32 a1, u32 a2, u32 a3, u32 b0, u32 b1)
{
    asm volatile(
        "mma.sync.aligned.m16n8k8.row.col.f32.tf32.tf32.f32 "
        "{%0,%1,%2,%3}, {%4,%5,%6,%7}, {%8,%9}, {%0,%1,%2,%3};"
        : "+f"(c0), "+f"(c1), "+f"(c2), "+f"(c3)
        : "r"(a0), "r"(a1), "r"(a2), "r"(a3), "r"(b0), "r"(b1));
}

extern __shared__ float smem_f[];

// Grid 128 = 8 pairs x 16 slices, 1 CTA/SM. Skewed single-pass scheme (R11):
// mma rows 0-7 = group gA step t, rows 8-15 = group gB step t-1.
// Warp w = hq*4+kq. Stage role: rows hq*4..hq*4+4 of k-strip kq (raw fp32;
// tf32 HMMA reads top bits). Poll role: lanes 0-15 poll the 16 (slice,row)
// flags this warp's stage needs, in parallel. Reduce role: warp w owns mma
// row w; publishes its own row flag (syncwarp + lane0 release).
__global__ void __launch_bounds__(THREADS, 1)
flipflop_main(const float* __restrict__ inputs,
              const float* __restrict__ Wv,
              const float* __restrict__ Pv,
              const float* __restrict__ bv,
              const float* __restrict__ Wz,
              const float* __restrict__ Pz,
              const float* __restrict__ bz,
              const float* __restrict__ fcW,
              const float* __restrict__ fcb,
              float* __restrict__ out,
              float* __restrict__ hidden)
{
    u32*   rW = (u32*)smem_f;                 // [16][RSTRIDE] fp32 bits, 33 KB
    float* ps = smem_f + 16 * RSTRIDE;        // 2 x [4kq][2][16rows][PSTRIDE]

    const int tid   = threadIdx.x;
    const int pair  = blockIdx.x >> 4;
    const int slice = blockIdx.x & 15;
    const int gA    = pair * 2, gB = gA + 1;
    const int gbA   = gA * BGr, gbB = gB * BGr;
    const int w     = tid >> 5;
    const int lane  = tid & 31;
    const int hq    = w >> 2;
    const int kq    = w & 3;
    const int g     = lane >> 2;
    const int t4    = lane & 3;
    const int hh    = lane;
    const int hg    = slice * HS + hh;

    // ---- B fragments (weights) in registers, tf32 RNA, 64 regs ----
    u32 bz0[16], bz1[16], bv0[16], bv1[16];
    {
        const int hB = slice * HS + hq * 8 + g;
        const float* zrow = Wz + (size_t)hB * NH + kq * 128 + t4;
        const float* vrow = Wv + (size_t)hB * NH + kq * 128 + t4;
        #pragma unroll
        for (int kb = 0; kb < 16; ++kb) {
            bz0[kb] = to_tf32(zrow[kb*8]);
            bz1[kb] = to_tf32(zrow[kb*8 + 4]);
            bv0[kb] = to_tf32(vrow[kb*8]);
            bv1[kb] = to_tf32(vrow[kb*8 + 4]);
        }
    }

    // parity probes (slots at t=NT-1 are rewritten only at launch end; group
    // CTAs are dataflow-coupled within +-1 iteration -> race-free at start)
    int parA, parB;
    asm volatile("ld.relaxed.gpu.global.s32 %0, [%1];"
                 : "=r"(parA) : "l"(&g_flag[gA][slice][0][NT-1]));
    asm volatile("ld.relaxed.gpu.global.s32 %0, [%1];"
                 : "=r"(parB) : "l"(&g_flag[gB][slice][0][NT-1]));
    const int readyA = parA ^ 1, readyB = parB ^ 1;

    // ---- reduce-role constants ----
    const float pz0 = Pz[hg*3+0], pz1 = Pz[hg*3+1], pz2 = Pz[hg*3+2];
    float pm0 = 0.f, pm1 = 0.f, pm2 = 0.f;        // P_m: bottom half zeroed
    if (hg < NH/2) { pm0 = Pv[hg*3+0]; pm1 = Pv[hg*3+1]; pm2 = Pv[hg*3+2]; }
    const float bzr = bz[hg];
    const float bvr = bv[hg];
    const int   rrow  = w & 7;
    const int   myrow = (w < 8) ? (gbA + rrow) : (gbB + rrow);
    const float* xrow = inputs + (size_t)myrow * NT * ND;
    float*       hout = hidden + ((size_t)myrow * NT) * NH + hg;
    int* myflag = (w < 8) ? &g_flag[gA][slice][rrow][0]
                          : &g_flag[gB][slice][rrow][0];
    const int myready = (w < 8) ? readyA : readyB;

    // ---- stage-role: warp stages tile rows [hq*4, hq*4+4) of k-strip kq ----
    const bool stA    = (hq < 2);                 // rows 0-7 <- group A
    const int  srow   = hq * 4 + (lane >> 3);     // tile row 0..15
    const int  sch    = (lane & 7) * 4;           // word chunk within window
    const int  sgrow  = stA ? (gbA + (srow & 7)) : (gbB + (srow & 7));
    const float* sg   = hidden + ((size_t)sgrow * NT) * NH + kq * 128 + sch;
    u32*        sd    = rW + srow * RSTRIDE + kq * 128 + sch;

    // ---- poll-role: lane l<16 polls (slice kq*4 + (l&3), group-row ...) ----
    const int  ps_s   = lane & 3;                 // producer slice within quad
    const int  ps_r   = (hq & 1) * 4 + (lane >> 2); // group row 0..7 (l<16)
    const int* pollp  = stA ? &g_flag[gA][kq*4 + ps_s][ps_r & 7][0]
                            : &g_flag[gB][kq*4 + ps_s][ps_r & 7][0];
    const int  pollpar = stA ? parA : parB;

    // ---- A-frag / psum indices ----
    const int ab0 = g * RSTRIDE + t4;
    const int ab1 = (g + 8) * RSTRIDE + t4;
    const int koff0 = kq * 128;
    const int psz_i = ((kq * 2 + 0) * 16 + g) * PSTRIDE + hq * 8 + t4 * 2;
    const int psv_i = ((kq * 2 + 1) * 16 + g) * PSTRIDE + hq * 8 + t4 * 2;

    // zero rW -> r0 = 0 for both groups
    for (int i = tid; i < 16 * RSTRIDE; i += THREADS) rW[i] = 0u;
    __syncthreads();

    float r_prev = 0.f;          // w<8: r_A(t-1)[row]; w>=8: r_B(t-2)[row]

    for (int t = 0; t <= NT; ++t) {
        // prefetch this warp's x (A: step t; B: step t-1)
        float x0 = 0.f, x1 = 0.f, x2 = 0.f;
        {
            const int xs = (w < 8) ? t : (t - 1);
            if (xs >= 0 && xs < NT) {
                x0 = xrow[xs*3+0]; x1 = xrow[xs*3+1]; x2 = xrow[xs*3+2];
            }
        }

        const bool do_stage = stA ? (t >= 1 && t < NT) : (t >= 2);
        const int  tsrc     = stA ? (t - 1) : (t - 2);

        // ---- poll: 16 lanes in parallel, one (slice,row) flag each ----
        if (do_stage && lane < 16)
            wait_flag(pollp + tsrc, pollpar);
        __syncwarp();

        // ---- stage: raw fp32 copy (tf32 HMMA ignores low mantissa bits) ----
        if (do_stage) {
            const float* s = sg + (size_t)tsrc * NH;
            #pragma unroll
            for (int j = 0; j < 4; ++j)                   // windows of 32 k
                *(uint4*)(sd + j * 32) = *(const uint4*)(s + j * 32);
        }
        asm volatile("bar.sync %0, 128;" :: "r"(kq + 1) : "memory");

        // ---- single mma pass: rows 0-7 = A(t), rows 8-15 = B(t-1) ----
        float* pb = ps + (t & 1) * PSUMW;
        if (t >= 1) {
            float cz0=0.f,cz1=0.f,cz2=0.f,cz3=0.f, cv0=0.f,cv1=0.f,cv2=0.f,cv3=0.f;
            #pragma unroll
            for (int kb = 0; kb < 16; ++kb) {
                const int ko = koff0 + kb * 8;
                u32 a0 = rW[ab0 + ko], a1 = rW[ab1 + ko];
                u32 a2 = rW[ab0 + ko + 4], a3 = rW[ab1 + ko + 4];
                mma_tf32(cz0,cz1,cz2,cz3, a0,a1,a2,a3, bz0[kb],bz1[kb]);
                mma_tf32(cv0,cv1,cv2,cv3, a0,a1,a2,a3, bv0[kb],bv1[kb]);
            }
            *(float2*)(pb + psz_i)               = make_float2(cz0, cz1);
            *(float2*)(pb + psz_i + 8 * PSTRIDE) = make_float2(cz2, cz3);
            *(float2*)(pb + psv_i)               = make_float2(cv0, cv1);
            *(float2*)(pb + psv_i + 8 * PSTRIDE) = make_float2(cv2, cv3);
        }
        __syncthreads();                          // psum complete (only CTA sync)

        // ---- reduce + gates + per-warp publish: warp w owns mma row w ----
        {
            const int xs   = (w < 8) ? t : (t - 1);      // step this warp emits
            const bool run = (xs >= 0) && (xs < NT);
            const bool hasp = (w < 8) ? (t >= 1) : (t >= 2);
            if (run) {
                float sz = 0.f, sv = 0.f;
                if (hasp) {
                    #pragma unroll
                    for (int q = 0; q < 4; ++q) {
                        sz += pb[((q*2 + 0) * 16 + w) * PSTRIDE + hh];
                        sv += pb[((q*2 + 1) * 16 + w) * PSTRIDE + hh];
                    }
                }
                const float az = sz + x0*pz0 + x1*pz1 + x2*pz2 + bzr;
                const float av = sv + x0*pm0 + x1*pm1 + x2*pm2 + bvr;
                const float z  = 1.f / (1.f + __expf(-az));
                const float c  = 1.f / (1.f + __expf(-av));
                const float rn = fmaf(z, c - r_prev, r_prev);
                r_prev = rn;
                hout[(size_t)xs * NH] = rn;
                __syncwarp();                     // order lane STGs before release
                if (hh == 0)
                    asm volatile("st.release.gpu.global.s32 [%0], %1;"
                                 :: "l"(myflag + xs), "r"(myready) : "memory");
            }
        }
    }

    // wait for every (group,row) final flag of this slice pair before fc
    if (lane < 8)       wait_flag(&g_flag[gA][w][lane][NT-1], parA);
    else if (lane < 16) wait_flag(&g_flag[gB][w][lane-8][NT-1], parB);
    __syncthreads();

    // ================= fc epilogue =================
    float* fw = smem_f;                           // reuse smem
    for (int i = tid; i < NC * NH; i += THREADS) fw[i] = fcW[i];
    const float fb0 = fcb[0], fb1 = fcb[1], fb2 = fcb[2];
    __syncthreads();

    float4 fw0[4], fw1[4], fw2[4];
    #pragma unroll
    for (int j = 0; j < 4; ++j) {
        const int i = hh + j * 32;
        fw0[j] = ((const float4*)(fw + 0 * NH))[i];
        fw1[j] = ((const float4*)(fw + 1 * NH))[i];
        fw2[j] = ((const float4*)(fw + 2 * NH))[i];
    }

    const int row = myrow;
    const int t0  = slice * (NT / NSLICE);
    const float* hp = hidden + ((size_t)row * NT + t0) * NH;
    float*       op = out    + ((size_t)row * NT + t0) * NC;

    for (int it = 0; it < NT / NSLICE; ++it) {
        const float4* h4 = (const float4*)(hp + (size_t)it * NH);
        float a0 = 0.f, a1 = 0.f, a2 = 0.f;
        #pragma unroll
        for (int j = 0; j < 4; ++j) {
            float4 h = h4[hh + j * 32];
            a0 += h.x*fw0[j].x + h.y*fw0[j].y + h.z*fw0[j].z + h.w*fw0[j].w;
            a1 += h.x*fw1[j].x + h.y*fw1[j].y + h.z*fw1[j].z + h.w*fw1[j].w;
            a2 += h.x*fw2[j].x + h.y*fw2[j].y + h.z*fw2[j].z + h.w*fw2[j].w;
        }
        #pragma unroll
        for (int o = 16; o; o >>= 1) {
            a0 += __shfl_down_sync(0xffffffffu, a0, o);
            a1 += __shfl_down_sync(0xffffffffu, a1, o);
            a2 += __shfl_down_sync(0xffffffffu, a2, o);
        }
        if (hh == 0) {
            op[it*3+0] = a0 + fb0;
            op[it*3+1] = a1 + fb1;
            op[it*3+2] = a2 + fb2;
        }
    }
}

extern "C" void kernel_launch(void* const* d_in, const int* in_sizes, int n_in,
                              void* d_out, int out_size)
{
    const float* inputs = (const float*)d_in[0];
    const float* Wv     = (const float*)d_in[1];
    const float* Pv     = (const float*)d_in[2];
    const float* b_v    = (const float*)d_in[3];
    const float* Wz     = (const float*)d_in[4];
    const float* Pz     = (const float*)d_in[5];
    const float* b_z    = (const float*)d_in[6];
    const float* fcW    = (const float*)d_in[7];
    const float* fcb    = (const float*)d_in[8];

    // outputs concatenated in reference return order: out (B,T,C) then hidden (B,T,H)
    float* out    = (float*)d_out;
    float* hidden = out + (size_t)NB * NT * NC;

    const int smem_bytes = (16 * RSTRIDE + 2 * PSUMW) * 4;
    cudaFuncSetAttribute(flipflop_main,
                         cudaFuncAttributeMaxDynamicSharedMemorySize, smem_bytes);

    flipflop_main<<<(NGRP / 2) * NSLICE, THREADS, smem_bytes>>>(
        inputs, Wv, Pv, b_v, Wz, Pz, b_z, fcW, fcb, out, hidden);
}